// round 10
// baseline (speedup 1.0000x reference)
#include <cuda_runtime.h>
#include <math.h>

#define NN 100000
#define BB 1024
#define LAT 128
#define INDIM 384      // NODE_DIM + 2*LATENT
#define FFNIN 512      // LATENT + IN_DIM
#define CAP 512
#define GQ 8           // queries per block in epi

// Scratch (device globals)
__device__ float g_qk[BB * INDIM];      // (Wk^T q) per query, incl. bqk
__device__ float g_hpart[BB * LAT];     // W1b @ q_input + b1
__device__ float g_acc[BB * INDIM];     // softmax-weighted kv sum
__device__ float g_Wqk[INDIM * INDIM];  // Wk^T @ Wq  (384x384)
__device__ float g_bqk[INDIM];          // Wk^T @ bq
__device__ float g_Wfold[LAT * INDIM];  // W1a @ Wv
__device__ float g_cvec[LAT];           // W1a @ bv
__device__ int   g_list[BB * CAP];
__device__ int   g_cnt[BB];

__device__ __forceinline__ float mrg(float a, float b, int bit, int lane) {
    float keep = (lane & bit) ? b : a;
    float send = (lane & bit) ? a : b;
    return keep + __shfl_xor_sync(0xffffffffu, send, bit);
}

// ---------------------------------------------------------------------------
// Kernel A (side): weight precompute. 128 blocks x 384 thr, 4 rows/block.
//   bi <  96: Wqk rows o=bi*4..+3:  Wqk[o][c] = sum_j Wk[j][o] Wq[j][c]; bqk
//   bi >= 96: Wfold rows o=(bi-96)*4: Wfold[o][c] = sum_j W1a[o][j] Wv[j][c]; cvec
// ---------------------------------------------------------------------------
__global__ void __launch_bounds__(384) k_weights(
    const float* __restrict__ Wq, const float* __restrict__ bq,
    const float* __restrict__ Wk, const float* __restrict__ Wv,
    const float* __restrict__ bv, const float* __restrict__ W1)
{
    int bi = blockIdx.x, t = threadIdx.x, lane = t & 31, w = t >> 5;
    __shared__ float wcol[4][LAT];
    bool qkpart = (bi < 96);
    int o0 = qkpart ? bi * 4 : (bi - 96) * 4;

    if (t < LAT) {
        if (qkpart) {
            float4 v = *(const float4*)&Wk[(size_t)t * INDIM + o0];
            wcol[0][t] = v.x; wcol[1][t] = v.y; wcol[2][t] = v.z; wcol[3][t] = v.w;
        } else {
            #pragma unroll
            for (int r = 0; r < 4; r++)
                wcol[r][t] = W1[(size_t)(o0 + r) * FFNIN + t];
        }
    }
    __syncthreads();

    // bias fold: warps 0..3 each compute one row's dot with bq/bv
    if (w < 4) {
        const float* bvec = qkpart ? bq : bv;
        float v = 0.f;
        #pragma unroll
        for (int i = 0; i < 4; i++) v = fmaf(wcol[w][lane + 32 * i], bvec[lane + 32 * i], v);
        #pragma unroll
        for (int off = 16; off; off >>= 1) v += __shfl_xor_sync(0xffffffffu, v, off);
        if (lane == 0) {
            if (qkpart) g_bqk[o0 + w] = v;
            else        g_cvec[o0 + w] = v;
        }
    }

    const float* M = qkpart ? Wq : Wv;        // both 128 x 384 row-major, contraction over rows
    float a0 = 0.f, a1 = 0.f, a2 = 0.f, a3 = 0.f;
    #pragma unroll 4
    for (int j = 0; j < LAT; j++) {
        float mv = M[(size_t)j * INDIM + t];
        a0 = fmaf(wcol[0][j], mv, a0);
        a1 = fmaf(wcol[1][j], mv, a1);
        a2 = fmaf(wcol[2][j], mv, a2);
        a3 = fmaf(wcol[3][j], mv, a3);
    }
    float* dst = qkpart ? g_Wqk : g_Wfold;
    dst[(size_t)(o0 + 0) * INDIM + t] = a0;
    dst[(size_t)(o0 + 1) * INDIM + t] = a1;
    dst[(size_t)(o0 + 2) * INDIM + t] = a2;
    dst[(size_t)(o0 + 3) * INDIM + t] = a3;
}

// ---------------------------------------------------------------------------
// Kernel B (side): prep GEMM. P[b][o] = qin[b] . Wcomb[o]  (o<384: Wqk->qk,
// o>=384: W1b->hpart). Tiled: 16 queries x 64 outputs per block, 256 thr,
// thread = (tq 0..15) x (to 0..15), 4 outputs each. grid (64, 8).
// ---------------------------------------------------------------------------
__global__ void __launch_bounds__(256) k_prep(
    const float* __restrict__ x, const float* __restrict__ mem,
    const float* __restrict__ tart, const int* __restrict__ tidx,
    const float* __restrict__ W1, const float* __restrict__ b1)
{
    int qt = blockIdx.x, ot = blockIdx.y;
    int b0 = qt * 16, o0 = ot * 64;
    int t = threadIdx.x;
    int tq = t >> 4, to = t & 15;

    __shared__ float qin_s[16][INDIM];
    __shared__ float w_s[32][65];
    __shared__ int sidx[16];

    if (t < 16) sidx[t] = tidx[b0 + t];
    __syncthreads();

    for (int m = t; m < 16 * 96; m += 256) {
        int q = m / 96, c4 = m % 96;
        float4 v;
        if (c4 < 32)      v = ((const float4*)(x    + (size_t)sidx[q] * LAT))[c4];
        else if (c4 < 64) v = ((const float4*)(mem  + (size_t)sidx[q] * LAT))[c4 - 32];
        else              v = ((const float4*)(tart + (size_t)(b0 + q) * LAT))[c4 - 64];
        *(float4*)&qin_s[q][c4 * 4] = v;
    }

    float acc[4] = {0.f, 0.f, 0.f, 0.f};
    bool qkpart = (ot < 6);

    for (int kt = 0; kt < INDIM; kt += 32) {
        __syncthreads();
        // stage weight tile: rows o0..o0+63, cols kt..kt+31 -> w_s[k][ocol]
        {
            int op = t >> 5, k = t & 31;
            #pragma unroll
            for (int rr = 0; rr < 8; rr++) {
                int ocol = rr * 8 + op;
                int row = o0 + ocol;
                float wv = qkpart ? g_Wqk[(size_t)row * INDIM + kt + k]
                                  : W1[(size_t)(row - INDIM) * FFNIN + LAT + kt + k];
                w_s[k][ocol] = wv;
            }
        }
        __syncthreads();
        #pragma unroll
        for (int k = 0; k < 32; k++) {
            float a = qin_s[tq][kt + k];
            #pragma unroll
            for (int j = 0; j < 4; j++)
                acc[j] = fmaf(a, w_s[k][to * 4 + j], acc[j]);
        }
    }

    int b = b0 + tq;
    #pragma unroll
    for (int j = 0; j < 4; j++) {
        int o = o0 + to * 4 + j;
        if (qkpart) g_qk[(size_t)b * INDIM + o] = acc[j] + g_bqk[o];
        else        g_hpart[(size_t)b * LAT + (o - INDIM)] = acc[j] + b1[o - INDIM];
    }
}

// ---------------------------------------------------------------------------
// Kernel 2: mask scan -> edge lists. 1024 x 256 (proven; 4-byte mask words).
// ---------------------------------------------------------------------------
#define PROC4(u, base) \
    if (u.x | u.y | u.z | u.w) { \
        if (u.x) { int sl = atomicAdd(&s_cnt, 1); if (sl < CAP) s_idx[sl] = (base) * 4 + 0; } \
        if (u.y) { int sl = atomicAdd(&s_cnt, 1); if (sl < CAP) s_idx[sl] = (base) * 4 + 1; } \
        if (u.z) { int sl = atomicAdd(&s_cnt, 1); if (sl < CAP) s_idx[sl] = (base) * 4 + 2; } \
        if (u.w) { int sl = atomicAdd(&s_cnt, 1); if (sl < CAP) s_idx[sl] = (base) * 4 + 3; } }

__global__ void __launch_bounds__(256) k_scan(
    const unsigned char* __restrict__ maskb, const int* __restrict__ tidx)
{
    int b = blockIdx.x, t = threadIdx.x;
    __shared__ int s_idx[CAP];
    __shared__ int s_cnt;
    if (t == 0) s_cnt = 0;
    __syncthreads();

    const uint4* row = (const uint4*)(maskb + (size_t)b * NN * 4);
    const int NW = NN / 4;
    int i = t;
    for (; i + 768 < NW; i += 1024) {
        uint4 a = row[i], b4 = row[i + 256], c4 = row[i + 512], d4 = row[i + 768];
        PROC4(a, i) PROC4(b4, i + 256) PROC4(c4, i + 512) PROC4(d4, i + 768)
    }
    for (; i < NW; i += 256) { uint4 u = row[i]; PROC4(u, i) }

    __syncthreads();
    int cnt = min(s_cnt, CAP);
    if (cnt == 0) {
        if (t == 0) { g_list[b * CAP] = tidx[b]; g_cnt[b] = 1; }
        return;
    }
    for (int m = t; m < cnt; m += 256) g_list[b * CAP + m] = s_idx[m];
    if (t == 0) g_cnt[b] = cnt;
}

// ---------------------------------------------------------------------------
// Kernel 3: gather + online softmax -> g_acc. 1024 x 512 (R7-proven, 26.7us).
// ---------------------------------------------------------------------------
__global__ void __launch_bounds__(512) k_gather(
    const float* __restrict__ x, const float* __restrict__ mem,
    const float* __restrict__ dt)
{
    int b = blockIdx.x, t = threadIdx.x, lane = t & 31, w = t >> 5;
    __shared__ float s_qk[INDIM];
    __shared__ float s_part[16][INDIM];
    __shared__ float s_m[16], s_l[16];

    if (t < INDIM) s_qk[t] = g_qk[(size_t)b * INDIM + t];
    __syncthreads();
    int cnt = g_cnt[b];
    const float scale = 0.08838834764831845f;   // 1/sqrt(128)

    float m = -INFINITY, l = 0.f;
    float racc[12];
    #pragma unroll
    for (int r = 0; r < 12; r++) racc[r] = 0.f;

    int p = w;
    float rowv[12];
    if (p < cnt) {
        int n = g_list[b * CAP + p];
        const float* px = x + (size_t)n * LAT;
        const float* pm = mem + (size_t)n * LAT;
        const float* pd = dt + (size_t)n * LAT;
        #pragma unroll
        for (int r = 0; r < 4; r++) rowv[r]     = px[lane + 32 * r];
        #pragma unroll
        for (int r = 0; r < 4; r++) rowv[4 + r] = pm[lane + 32 * r];
        #pragma unroll
        for (int r = 0; r < 4; r++) rowv[8 + r] = pd[lane + 32 * r];
    }
    while (p < cnt) {
        int pn = p + 16;
        float rnext[12];
        if (pn < cnt) {
            int n = g_list[b * CAP + pn];
            const float* px = x + (size_t)n * LAT;
            const float* pm = mem + (size_t)n * LAT;
            const float* pd = dt + (size_t)n * LAT;
            #pragma unroll
            for (int r = 0; r < 4; r++) rnext[r]     = px[lane + 32 * r];
            #pragma unroll
            for (int r = 0; r < 4; r++) rnext[4 + r] = pm[lane + 32 * r];
            #pragma unroll
            for (int r = 0; r < 4; r++) rnext[8 + r] = pd[lane + 32 * r];
        }
        float dot = 0.f;
        #pragma unroll
        for (int r = 0; r < 12; r++) dot = fmaf(rowv[r], s_qk[32 * r + lane], dot);
        #pragma unroll
        for (int off = 16; off; off >>= 1) dot += __shfl_xor_sync(0xffffffffu, dot, off);
        float s = dot * scale;                  // q.bk dropped (softmax-invariant)
        float mnew = fmaxf(m, s);
        float corr = __expf(m - mnew);
        float e = __expf(s - mnew);
        l = l * corr + e;
        m = mnew;
        #pragma unroll
        for (int r = 0; r < 12; r++) racc[r] = fmaf(racc[r], corr, e * rowv[r]);
        #pragma unroll
        for (int r = 0; r < 12; r++) rowv[r] = rnext[r];
        p = pn;
    }
    #pragma unroll
    for (int r = 0; r < 12; r++) s_part[w][32 * r + lane] = racc[r];
    if (lane == 0) { s_m[w] = m; s_l[w] = l; }
    __syncthreads();

    float M = s_m[0];
    #pragma unroll
    for (int i = 1; i < 16; i++) M = fmaxf(M, s_m[i]);
    float L = 0.f;
    float ef[16];
    #pragma unroll
    for (int i = 0; i < 16; i++) { ef[i] = __expf(s_m[i] - M); L += s_l[i] * ef[i]; }
    float invL = 1.f / L;
    if (t < INDIM) {
        float sum = 0.f;
        #pragma unroll
        for (int i = 0; i < 16; i++) sum = fmaf(s_part[i][t], ef[i], sum);
        g_acc[(size_t)b * INDIM + t] = sum * invL;
    }
}

// ---------------------------------------------------------------------------
// Kernel 4: folded epilogue (R7-proven). 128 blocks x 512, GQ=8.
//   h = relu(Wfold @ acc + hpart + cvec) ; out = W2 @ h + b2
// ---------------------------------------------------------------------------
__global__ void __launch_bounds__(512) k_epi(
    const float* __restrict__ W2, const float* __restrict__ b2,
    float* __restrict__ out)
{
    int b0 = blockIdx.x * GQ;
    int t = threadIdx.x, lane = t & 31, w = t >> 5;
    __shared__ float acc[GQ][INDIM];
    __shared__ float hp[GQ][LAT];
    __shared__ float h[GQ][LAT];

    for (int m = t; m < GQ * 96; m += 512) {
        int q = m / 96, c4 = m % 96;
        *(float4*)&acc[q][c4 * 4] = *(const float4*)&g_acc[(size_t)(b0 + q) * INDIM + c4 * 4];
    }
    for (int m = t; m < GQ * LAT; m += 512) {
        int q = m >> 7, o = m & 127;
        hp[q][o] = g_hpart[(size_t)(b0 + q) * LAT + o] + g_cvec[o];
    }
    __syncthreads();

    for (int oi = 0; oi < 8; oi++) {
        int o = w * 8 + oi;
        const float* wr = g_Wfold + (size_t)o * INDIM;
        float wreg[12];
        #pragma unroll
        for (int r = 0; r < 12; r++) wreg[r] = wr[lane + 32 * r];
        float p[GQ];
        #pragma unroll
        for (int q = 0; q < GQ; q++) {
            float s = 0.f;
            #pragma unroll
            for (int r = 0; r < 12; r++) s = fmaf(wreg[r], acc[q][lane + 32 * r], s);
            p[q] = s;
        }
        float a0 = mrg(p[0], p[1], 16, lane), a1 = mrg(p[2], p[3], 16, lane);
        float a2 = mrg(p[4], p[5], 16, lane), a3 = mrg(p[6], p[7], 16, lane);
        float b4 = mrg(a0, a1, 8, lane), b5 = mrg(a2, a3, 8, lane);
        float c0 = mrg(b4, b5, 4, lane);
        c0 += __shfl_xor_sync(0xffffffffu, c0, 1);
        c0 += __shfl_xor_sync(0xffffffffu, c0, 2);
        if ((lane & 3) == 0) {
            int q = ((lane >> 4) & 1) + ((lane >> 2) & 2) + (lane & 4);
            h[q][o] = fmaxf(c0 + hp[q][o], 0.f);
        }
    }
    __syncthreads();

    for (int oi = 0; oi < 8; oi++) {
        int o = w * 8 + oi;
        const float* wr = W2 + (size_t)o * LAT;
        float wreg[4];
        #pragma unroll
        for (int r = 0; r < 4; r++) wreg[r] = wr[lane + 32 * r];
        float p[GQ];
        #pragma unroll
        for (int q = 0; q < GQ; q++) {
            float s = 0.f;
            #pragma unroll
            for (int r = 0; r < 4; r++) s = fmaf(wreg[r], h[q][lane + 32 * r], s);
            p[q] = s;
        }
        float a0 = mrg(p[0], p[1], 16, lane), a1 = mrg(p[2], p[3], 16, lane);
        float a2 = mrg(p[4], p[5], 16, lane), a3 = mrg(p[6], p[7], 16, lane);
        float b4 = mrg(a0, a1, 8, lane), b5 = mrg(a2, a3, 8, lane);
        float c0 = mrg(b4, b5, 4, lane);
        c0 += __shfl_xor_sync(0xffffffffu, c0, 1);
        c0 += __shfl_xor_sync(0xffffffffu, c0, 2);
        float bias = b2[o];
        if ((lane & 3) == 0) {
            int q = ((lane >> 4) & 1) + ((lane >> 2) & 2) + (lane & 4);
            out[(size_t)(b0 + q) * LAT + o] = c0 + bias;
        }
    }
}

// ---------------------------------------------------------------------------
extern "C" void kernel_launch(void* const* d_in, const int* in_sizes, int n_in,
                              void* d_out, int out_size)
{
    const float* x    = (const float*)d_in[0];
    const float* mem  = (const float*)d_in[1];
    const float* dt   = (const float*)d_in[2];
    const float* tart = (const float*)d_in[3];
    const unsigned char* mask = (const unsigned char*)d_in[4];
    const int*   tidx = (const int*)d_in[5];
    const float* Wq = (const float*)d_in[6];
    const float* bq = (const float*)d_in[7];
    const float* Wk = (const float*)d_in[8];
    // bk (d_in[9]) unused: q.bk cancels in softmax
    const float* Wv = (const float*)d_in[10];
    const float* bv = (const float*)d_in[11];
    const float* W1 = (const float*)d_in[12];
    const float* b1 = (const float*)d_in[13];
    const float* W2 = (const float*)d_in[14];
    const float* b2 = (const float*)d_in[15];
    float* out = (float*)d_out;

    static cudaStream_t s_side = nullptr;
    static cudaEvent_t e_fork = nullptr, e_join = nullptr;
    if (s_side == nullptr) {
        cudaStreamCreateWithFlags(&s_side, cudaStreamNonBlocking);
        cudaEventCreateWithFlags(&e_fork, cudaEventDisableTiming);
        cudaEventCreateWithFlags(&e_join, cudaEventDisableTiming);
    }

    cudaEventRecord(e_fork, 0);
    cudaStreamWaitEvent(s_side, e_fork, 0);
    k_weights<<<128, 384, 0, s_side>>>(Wq, bq, Wk, Wv, bv, W1);
    k_prep<<<dim3(64, 8), 256, 0, s_side>>>(x, mem, tart, tidx, W1, b1);
    cudaEventRecord(e_join, s_side);

    k_scan<<<BB, 256>>>(mask, tidx);

    cudaStreamWaitEvent(0, e_join, 0);
    k_gather<<<BB, 512>>>(x, mem, dt);
    k_epi<<<BB / GQ, 512>>>(W2, b2, out);
}

// round 11
// speedup vs baseline: 1.3176x; 1.3176x over previous
#include <cuda_runtime.h>
#include <math.h>

// Problem constants (fixed shapes per reference)
#define NN 100000
#define BB 1024
#define LAT 128
#define INDIM 384      // NODE_DIM + 2*LATENT
#define FFNIN 512      // LATENT + IN_DIM
#define CAP 512        // neighbor list capacity (mean ~50)
#define GQ 8           // queries per block in prep

// Scratch (device globals; no allocation allowed)
__device__ float g_qk[BB * INDIM];
__device__ float g_hpart[BB * LAT];     // W1b @ q_input + b1
__device__ float g_Wfold[LAT * INDIM];  // W1a @ Wv
__device__ float g_cvec[LAT];           // W1a @ bv
__device__ int   g_list[BB * CAP];
__device__ int   g_cnt[BB];

// Merge two partial-sum arrays across xor-lane distance `bit`
__device__ __forceinline__ float mrg(float a, float b, int bit, int lane) {
    float keep = (lane & bit) ? b : a;
    float send = (lane & bit) ? a : b;
    return keep + __shfl_xor_sync(0xffffffffu, send, bit);
}

// ---------------------------------------------------------------------------
// Kernel 1 (side stream): prep + fold. 128 blocks x 512 threads, <=64 regs.
//   Per block: GQ=8 queries:
//     qin = [x[idx], mem[idx], tar_t]; q = Wq@qin + bq; qk = Wk^T q
//     hpart = W1b@qin + b1
//   Plus one Wfold row: Wfold[o] = W1a[o] @ Wv ; cvec[o] = W1a[o].bv  (o=blockIdx)
//   q.bk dropped: constant per query, cancels in softmax.
//   Multi-reduce runs in TWO groups of 4 queries to keep register count low
//   (R8 did all 8 at once -> 128 regs -> 1 block/SM -> 42.6us).
// ---------------------------------------------------------------------------
__global__ void __launch_bounds__(512, 2) k_prep(
    const float* __restrict__ x, const float* __restrict__ mem,
    const float* __restrict__ tart, const int* __restrict__ tidx,
    const float* __restrict__ Wq, const float* __restrict__ bq,
    const float* __restrict__ Wk, const float* __restrict__ W1,
    const float* __restrict__ b1, const float* __restrict__ Wv,
    const float* __restrict__ bv)
{
    int b0 = blockIdx.x * GQ;
    int t = threadIdx.x, lane = t & 31, w = t >> 5;
    __shared__ float qin[GQ][INDIM];
    __shared__ float qsm[GQ][LAT];
    __shared__ float wk_sm[16][INDIM];
    __shared__ float w1a[LAT];
    __shared__ float s_cvec;
    __shared__ int sidx[GQ];

    if (t < GQ) sidx[t] = tidx[b0 + t];
    if (t < LAT) w1a[t] = W1[(size_t)blockIdx.x * FFNIN + t];
    __syncthreads();

    // ---- Wfold row: Wfold[o][c] = sum_j w1a[j] * Wv[j][c]  (o = blockIdx) ----
    if (t < INDIM) {
        float s = 0.f;
        #pragma unroll 8
        for (int j = 0; j < LAT; j++) s = fmaf(w1a[j], Wv[(size_t)j * INDIM + t], s);
        g_Wfold[(size_t)blockIdx.x * INDIM + t] = s;
    }
    // cvec[o] = w1a . bv
    if (w == 15) {
        float v = 0.f;
        #pragma unroll
        for (int r = 0; r < 4; r++) v = fmaf(w1a[lane + 32 * r], bv[lane + 32 * r], v);
        #pragma unroll
        for (int off = 16; off; off >>= 1) v += __shfl_xor_sync(0xffffffffu, v, off);
        if (lane == 0) s_cvec = v;
    }

    // ---- gather q_input ----
    for (int m = t; m < GQ * 96; m += 512) {
        int q = m / 96, c4 = m % 96;
        float4 v;
        if (c4 < 32)      v = ((const float4*)(x    + (size_t)sidx[q] * LAT))[c4];
        else if (c4 < 64) v = ((const float4*)(mem  + (size_t)sidx[q] * LAT))[c4 - 32];
        else              v = ((const float4*)(tart + (size_t)(b0 + q) * LAT))[c4 - 64];
        *(float4*)&qin[q][c4 * 4] = v;
    }
    __syncthreads();

    // ---- q = Wq @ qin + bq  (16 warps x 8 outputs; 2 groups of 4 queries) ----
    for (int oi = 0; oi < 8; oi++) {
        int o = w * 8 + oi;
        const float* wr = Wq + (size_t)o * INDIM;
        float wreg[12];
        #pragma unroll
        for (int r = 0; r < 12; r++) wreg[r] = wr[lane + 32 * r];
        float bias = bq[o];
        #pragma unroll
        for (int g = 0; g < 2; g++) {
            float p[4];
            #pragma unroll
            for (int qq = 0; qq < 4; qq++) {
                float s = 0.f;
                #pragma unroll
                for (int r = 0; r < 12; r++) s = fmaf(wreg[r], qin[g * 4 + qq][lane + 32 * r], s);
                p[qq] = s;
            }
            float a0 = mrg(p[0], p[1], 16, lane), a1 = mrg(p[2], p[3], 16, lane);
            float c0 = mrg(a0, a1, 8, lane);
            c0 += __shfl_xor_sync(0xffffffffu, c0, 4);
            c0 += __shfl_xor_sync(0xffffffffu, c0, 2);
            c0 += __shfl_xor_sync(0xffffffffu, c0, 1);
            if ((lane & 7) == 0) {
                int q = g * 4 + ((lane >> 4) & 1) + ((lane >> 3) & 1) * 2;
                qsm[q][o] = c0 + bias;
            }
        }
    }

    // ---- hpart = W1b @ qin + b1  (same structure) ----
    for (int oi = 0; oi < 8; oi++) {
        int o = w * 8 + oi;
        const float* wr = W1 + (size_t)o * FFNIN + LAT;
        float wreg[12];
        #pragma unroll
        for (int r = 0; r < 12; r++) wreg[r] = wr[lane + 32 * r];
        float bias = b1[o];
        #pragma unroll
        for (int g = 0; g < 2; g++) {
            float p[4];
            #pragma unroll
            for (int qq = 0; qq < 4; qq++) {
                float s = 0.f;
                #pragma unroll
                for (int r = 0; r < 12; r++) s = fmaf(wreg[r], qin[g * 4 + qq][lane + 32 * r], s);
                p[qq] = s;
            }
            float a0 = mrg(p[0], p[1], 16, lane), a1 = mrg(p[2], p[3], 16, lane);
            float c0 = mrg(a0, a1, 8, lane);
            c0 += __shfl_xor_sync(0xffffffffu, c0, 4);
            c0 += __shfl_xor_sync(0xffffffffu, c0, 2);
            c0 += __shfl_xor_sync(0xffffffffu, c0, 1);
            if ((lane & 7) == 0) {
                int q = g * 4 + ((lane >> 4) & 1) + ((lane >> 3) & 1) * 2;
                g_hpart[(size_t)(b0 + q) * LAT + o] = c0 + bias;
            }
        }
    }
    __syncthreads();

    // ---- qk = Wk^T q  (smem-staged Wk tiles) ----
    float acc[GQ];
    #pragma unroll
    for (int q = 0; q < GQ; q++) acc[q] = 0.f;
    for (int j0 = 0; j0 < LAT; j0 += 16) {
        __syncthreads();
        for (int m = t; m < 16 * 96; m += 512) {
            int jj = m / 96, c4 = m % 96;
            *(float4*)&wk_sm[jj][c4 * 4] =
                ((const float4*)(Wk + (size_t)(j0 + jj) * INDIM))[c4];
        }
        __syncthreads();
        if (t < INDIM) {
            #pragma unroll
            for (int jj = 0; jj < 16; jj++) {
                float wv = wk_sm[jj][t];
                #pragma unroll
                for (int q = 0; q < GQ; q++) acc[q] = fmaf(qsm[q][j0 + jj], wv, acc[q]);
            }
        }
    }
    if (t < INDIM) {
        #pragma unroll
        for (int q = 0; q < GQ; q++) g_qk[(size_t)(b0 + q) * INDIM + t] = acc[q];
    }
    if (t == 0) g_cvec[blockIdx.x] = s_cvec;
}

// ---------------------------------------------------------------------------
// Kernel 2: mask scan -> edge lists. 1024 blocks x 256 thr (proven config).
// Mask is 4-byte elements (traffic-proven): word != 0 <=> edge.
// ---------------------------------------------------------------------------
#define PROC4(u, base) \
    if (u.x | u.y | u.z | u.w) { \
        if (u.x) { int sl = atomicAdd(&s_cnt, 1); if (sl < CAP) s_idx[sl] = (base) * 4 + 0; } \
        if (u.y) { int sl = atomicAdd(&s_cnt, 1); if (sl < CAP) s_idx[sl] = (base) * 4 + 1; } \
        if (u.z) { int sl = atomicAdd(&s_cnt, 1); if (sl < CAP) s_idx[sl] = (base) * 4 + 2; } \
        if (u.w) { int sl = atomicAdd(&s_cnt, 1); if (sl < CAP) s_idx[sl] = (base) * 4 + 3; } }

__global__ void __launch_bounds__(256) k_scan(
    const unsigned char* __restrict__ maskb, const int* __restrict__ tidx)
{
    int b = blockIdx.x, t = threadIdx.x;
    __shared__ int s_idx[CAP];
    __shared__ int s_cnt;
    if (t == 0) s_cnt = 0;
    __syncthreads();

    const uint4* row = (const uint4*)(maskb + (size_t)b * NN * 4);
    const int NW = NN / 4;                    // 25000 uint4
    int i = t;
    for (; i + 768 < NW; i += 1024) {
        uint4 a = row[i], b4 = row[i + 256], c4 = row[i + 512], d4 = row[i + 768];
        PROC4(a, i) PROC4(b4, i + 256) PROC4(c4, i + 512) PROC4(d4, i + 768)
    }
    for (; i < NW; i += 256) { uint4 u = row[i]; PROC4(u, i) }

    __syncthreads();
    int cnt = min(s_cnt, CAP);
    if (cnt == 0) {
        if (t == 0) { g_list[b * CAP] = tidx[b]; g_cnt[b] = 1; }
        return;
    }
    for (int m = t; m < cnt; m += 256) g_list[b * CAP + m] = s_idx[m];
    if (t == 0) g_cnt[b] = cnt;
}

// ---------------------------------------------------------------------------
// Kernel 3: gather + online softmax + folded FFN epilogue (R8 verbatim).
// 1024 blocks x 512 thr. Writes final output directly.
// ---------------------------------------------------------------------------
__global__ void __launch_bounds__(512, 2) k_gather(
    const float* __restrict__ x, const float* __restrict__ mem,
    const float* __restrict__ dt, const float* __restrict__ W2,
    const float* __restrict__ b2, float* __restrict__ out)
{
    int b = blockIdx.x, t = threadIdx.x, lane = t & 31, w = t >> 5;
    __shared__ float s_qk[INDIM];
    __shared__ float s_part[16][INDIM];
    __shared__ float s_m[16], s_l[16];
    __shared__ float s_acc[INDIM];
    __shared__ float s_hp[LAT];
    __shared__ float s_h[LAT];

    if (t < INDIM) s_qk[t] = g_qk[(size_t)b * INDIM + t];
    if (t >= INDIM && t < INDIM + LAT) {
        int o = t - INDIM;
        s_hp[o] = g_hpart[(size_t)b * LAT + o] + g_cvec[o];
    }
    __syncthreads();
    int cnt = g_cnt[b];
    const float scale = 0.08838834764831845f;   // 1/sqrt(128)

    float m = -INFINITY, l = 0.f;
    float racc[12];
    #pragma unroll
    for (int r = 0; r < 12; r++) racc[r] = 0.f;

    int p = w;
    float rowv[12];
    if (p < cnt) {
        int n = g_list[b * CAP + p];
        const float* px = x + (size_t)n * LAT;
        const float* pm = mem + (size_t)n * LAT;
        const float* pd = dt + (size_t)n * LAT;
        #pragma unroll
        for (int r = 0; r < 4; r++) rowv[r]     = px[lane + 32 * r];
        #pragma unroll
        for (int r = 0; r < 4; r++) rowv[4 + r] = pm[lane + 32 * r];
        #pragma unroll
        for (int r = 0; r < 4; r++) rowv[8 + r] = pd[lane + 32 * r];
    }
    while (p < cnt) {
        int pn = p + 16;
        float rnext[12];
        if (pn < cnt) {
            int n = g_list[b * CAP + pn];
            const float* px = x + (size_t)n * LAT;
            const float* pm = mem + (size_t)n * LAT;
            const float* pd = dt + (size_t)n * LAT;
            #pragma unroll
            for (int r = 0; r < 4; r++) rnext[r]     = px[lane + 32 * r];
            #pragma unroll
            for (int r = 0; r < 4; r++) rnext[4 + r] = pm[lane + 32 * r];
            #pragma unroll
            for (int r = 0; r < 4; r++) rnext[8 + r] = pd[lane + 32 * r];
        }
        float dot = 0.f;
        #pragma unroll
        for (int r = 0; r < 12; r++) dot = fmaf(rowv[r], s_qk[32 * r + lane], dot);
        #pragma unroll
        for (int off = 16; off; off >>= 1) dot += __shfl_xor_sync(0xffffffffu, dot, off);
        float s = dot * scale;                  // qbias dropped: softmax shift-invariant
        float mnew = fmaxf(m, s);
        float corr = __expf(m - mnew);
        float e = __expf(s - mnew);
        l = l * corr + e;
        m = mnew;
        #pragma unroll
        for (int r = 0; r < 12; r++) racc[r] = fmaf(racc[r], corr, e * rowv[r]);
        #pragma unroll
        for (int r = 0; r < 12; r++) rowv[r] = rnext[r];
        p = pn;
    }
    #pragma unroll
    for (int r = 0; r < 12; r++) s_part[w][32 * r + lane] = racc[r];
    if (lane == 0) { s_m[w] = m; s_l[w] = l; }
    __syncthreads();

    // merge 16 warp-local online-softmax states -> s_acc
    {
        float M = s_m[0];
        #pragma unroll
        for (int i = 1; i < 16; i++) M = fmaxf(M, s_m[i]);
        float L = 0.f;
        float ef[16];
        #pragma unroll
        for (int i = 0; i < 16; i++) { ef[i] = __expf(s_m[i] - M); L += s_l[i] * ef[i]; }
        float invL = 1.f / L;
        if (t < INDIM) {
            float sum = 0.f;
            #pragma unroll
            for (int i = 0; i < 16; i++) sum = fmaf(s_part[i][t], ef[i], sum);
            s_acc[t] = sum * invL;
        }
    }
    __syncthreads();

    // FFN stage 1: h = relu(Wfold @ acc + hpart)
    for (int oi = 0; oi < 8; oi++) {
        int o = w * 8 + oi;
        const float* wr = g_Wfold + (size_t)o * INDIM;
        float dot = 0.f;
        #pragma unroll
        for (int r = 0; r < 12; r++) dot = fmaf(wr[lane + 32 * r], s_acc[lane + 32 * r], dot);
        #pragma unroll
        for (int off = 16; off; off >>= 1) dot += __shfl_xor_sync(0xffffffffu, dot, off);
        if (lane == 0) s_h[o] = fmaxf(dot + s_hp[o], 0.f);
    }
    __syncthreads();

    // FFN stage 2: out = W2 @ h + b2
    for (int oi = 0; oi < 8; oi++) {
        int o = w * 8 + oi;
        const float* wr = W2 + (size_t)o * LAT;
        float dot = 0.f;
        #pragma unroll
        for (int r = 0; r < 4; r++) dot = fmaf(wr[lane + 32 * r], s_h[lane + 32 * r], dot);
        #pragma unroll
        for (int off = 16; off; off >>= 1) dot += __shfl_xor_sync(0xffffffffu, dot, off);
        if (lane == 0) out[(size_t)b * LAT + o] = dot + b2[o];
    }
}

// ---------------------------------------------------------------------------
extern "C" void kernel_launch(void* const* d_in, const int* in_sizes, int n_in,
                              void* d_out, int out_size)
{
    const float* x    = (const float*)d_in[0];
    const float* mem  = (const float*)d_in[1];
    const float* dt   = (const float*)d_in[2];
    const float* tart = (const float*)d_in[3];
    const unsigned char* mask = (const unsigned char*)d_in[4];
    const int*   tidx = (const int*)d_in[5];
    const float* Wq = (const float*)d_in[6];
    const float* bq = (const float*)d_in[7];
    const float* Wk = (const float*)d_in[8];
    // bk (d_in[9]) unused: q.bk cancels in softmax
    const float* Wv = (const float*)d_in[10];
    const float* bv = (const float*)d_in[11];
    const float* W1 = (const float*)d_in[12];
    const float* b1 = (const float*)d_in[13];
    const float* W2 = (const float*)d_in[14];
    const float* b2 = (const float*)d_in[15];
    float* out = (float*)d_out;

    // Fork-join: prep+fold (weights path) concurrent with scan (mask path).
    static cudaStream_t s_side = nullptr;
    static cudaEvent_t e_fork = nullptr, e_join = nullptr;
    if (s_side == nullptr) {
        cudaStreamCreateWithFlags(&s_side, cudaStreamNonBlocking);
        cudaEventCreateWithFlags(&e_fork, cudaEventDisableTiming);
        cudaEventCreateWithFlags(&e_join, cudaEventDisableTiming);
    }

    cudaEventRecord(e_fork, 0);
    cudaStreamWaitEvent(s_side, e_fork, 0);
    k_prep<<<BB / GQ, 512, 0, s_side>>>(x, mem, tart, tidx, Wq, bq, Wk, W1, b1, Wv, bv);
    cudaEventRecord(e_join, s_side);

    k_scan<<<BB, 256>>>(mask, tidx);

    cudaStreamWaitEvent(0, e_join, 0);
    k_gather<<<BB, 512>>>(x, mem, dt, W2, b2, out);
}

// round 12
// speedup vs baseline: 1.3423x; 1.0187x over previous
#include <cuda_runtime.h>
#include <math.h>

// Problem constants (fixed shapes per reference)
#define NN 100000
#define BB 1024
#define LAT 128
#define INDIM 384      // NODE_DIM + 2*LATENT
#define FFNIN 512      // LATENT + IN_DIM
#define CAP 512        // neighbor list capacity (mean ~50)
#define GQ 8           // queries per prep block
#define PREPB 128      // number of prep blocks (BB/GQ)

// Scratch (device globals; no allocation allowed)
__device__ float g_qk[BB * INDIM];
__device__ float g_hpart[BB * LAT];     // W1b @ q_input + b1
__device__ float g_Wfold[LAT * INDIM];  // W1a @ Wv
__device__ float g_cvec[LAT];           // W1a @ bv
__device__ int   g_list[BB * CAP];
__device__ int   g_cnt[BB];

// Merge two partial-sum arrays across xor-lane distance `bit`
__device__ __forceinline__ float mrg(float a, float b, int bit, int lane) {
    float keep = (lane & bit) ? b : a;
    float send = (lane & bit) ? a : b;
    return keep + __shfl_xor_sync(0xffffffffu, send, bit);
}

// Shared-memory union: prep path needs ~41.5KB, scan path ~2KB.
struct SmemPrep {
    float qin[GQ][INDIM];
    float qsm[GQ][LAT];
    float wk_sm[16][INDIM];
    float w1a[LAT];
    float cvec;
    int   sidx[GQ];
};
struct SmemScan {
    int idx[CAP];
    int cnt;
};
union SmemU {
    SmemPrep p;
    SmemScan s;
};

#define PROC4(u, base) \
    if (u.x | u.y | u.z | u.w) { \
        if (u.x) { int sl = atomicAdd(cntp, 1); if (sl < CAP) idxp[sl] = (base) * 4 + 0; } \
        if (u.y) { int sl = atomicAdd(cntp, 1); if (sl < CAP) idxp[sl] = (base) * 4 + 1; } \
        if (u.z) { int sl = atomicAdd(cntp, 1); if (sl < CAP) idxp[sl] = (base) * 4 + 2; } \
        if (u.w) { int sl = atomicAdd(cntp, 1); if (sl < CAP) idxp[sl] = (base) * 4 + 3; } }

// ---------------------------------------------------------------------------
// FAT kernel: blocks [0,128) = prep ; blocks [128, 128+1024) = scan.
// Prep (latency-bound, no DRAM) co-schedules with scan (DRAM-bound) from
// wave 1: structural overlap, no streams needed.
// ---------------------------------------------------------------------------
__global__ void __launch_bounds__(512, 2) k_main(
    const float* __restrict__ x, const float* __restrict__ mem,
    const float* __restrict__ tart, const int* __restrict__ tidx,
    const float* __restrict__ Wq, const float* __restrict__ bq,
    const float* __restrict__ Wk, const float* __restrict__ W1,
    const float* __restrict__ b1, const float* __restrict__ Wv,
    const float* __restrict__ bv, const unsigned char* __restrict__ maskb)
{
    __shared__ SmemU su;
    int t = threadIdx.x, lane = t & 31, w = t >> 5;

    if (blockIdx.x >= PREPB) {
        // ================= SCAN PATH (512 threads) =================
        int b = blockIdx.x - PREPB;
        int* idxp = su.s.idx;
        int* cntp = &su.s.cnt;
        if (t == 0) *cntp = 0;
        __syncthreads();

        const uint4* row = (const uint4*)(maskb + (size_t)b * NN * 4);
        const int NW = NN / 4;                    // 25000 uint4
        int i = t;
        for (; i + 1536 < NW; i += 2048) {
            uint4 a  = row[i];
            uint4 b4 = row[i + 512];
            uint4 c4 = row[i + 1024];
            uint4 d4 = row[i + 1536];
            PROC4(a, i) PROC4(b4, i + 512) PROC4(c4, i + 1024) PROC4(d4, i + 1536)
        }
        for (; i < NW; i += 512) { uint4 u = row[i]; PROC4(u, i) }

        __syncthreads();
        int cnt = min(*cntp, CAP);
        if (cnt == 0) {
            if (t == 0) { g_list[b * CAP] = tidx[b]; g_cnt[b] = 1; }
            return;
        }
        for (int m2 = t; m2 < cnt; m2 += 512) g_list[b * CAP + m2] = idxp[m2];
        if (t == 0) g_cnt[b] = cnt;
        return;
    }

    // ================= PREP PATH (R11-verbatim logic) =================
    int b0 = blockIdx.x * GQ;
    if (t < GQ) su.p.sidx[t] = tidx[b0 + t];
    if (t < LAT) su.p.w1a[t] = W1[(size_t)blockIdx.x * FFNIN + t];
    __syncthreads();

    // Wfold row: Wfold[o][c] = sum_j w1a[j] * Wv[j][c]  (o = blockIdx)
    if (t < INDIM) {
        float s = 0.f;
        #pragma unroll 8
        for (int j = 0; j < LAT; j++) s = fmaf(su.p.w1a[j], Wv[(size_t)j * INDIM + t], s);
        g_Wfold[(size_t)blockIdx.x * INDIM + t] = s;
    }
    // cvec[o] = w1a . bv
    if (w == 15) {
        float v = 0.f;
        #pragma unroll
        for (int r = 0; r < 4; r++) v = fmaf(su.p.w1a[lane + 32 * r], bv[lane + 32 * r], v);
        #pragma unroll
        for (int off = 16; off; off >>= 1) v += __shfl_xor_sync(0xffffffffu, v, off);
        if (lane == 0) su.p.cvec = v;
    }

    // gather q_input
    for (int m2 = t; m2 < GQ * 96; m2 += 512) {
        int q = m2 / 96, c4 = m2 % 96;
        float4 v;
        if (c4 < 32)      v = ((const float4*)(x    + (size_t)su.p.sidx[q] * LAT))[c4];
        else if (c4 < 64) v = ((const float4*)(mem  + (size_t)su.p.sidx[q] * LAT))[c4 - 32];
        else              v = ((const float4*)(tart + (size_t)(b0 + q) * LAT))[c4 - 64];
        *(float4*)&su.p.qin[q][c4 * 4] = v;
    }
    __syncthreads();

    // q = Wq @ qin + bq  (16 warps x 8 outputs; 2 groups of 4 queries)
    for (int oi = 0; oi < 8; oi++) {
        int o = w * 8 + oi;
        const float* wr = Wq + (size_t)o * INDIM;
        float wreg[12];
        #pragma unroll
        for (int r = 0; r < 12; r++) wreg[r] = wr[lane + 32 * r];
        float bias = bq[o];
        #pragma unroll
        for (int g = 0; g < 2; g++) {
            float p[4];
            #pragma unroll
            for (int qq = 0; qq < 4; qq++) {
                float s = 0.f;
                #pragma unroll
                for (int r = 0; r < 12; r++)
                    s = fmaf(wreg[r], su.p.qin[g * 4 + qq][lane + 32 * r], s);
                p[qq] = s;
            }
            float a0 = mrg(p[0], p[1], 16, lane), a1 = mrg(p[2], p[3], 16, lane);
            float c0 = mrg(a0, a1, 8, lane);
            c0 += __shfl_xor_sync(0xffffffffu, c0, 4);
            c0 += __shfl_xor_sync(0xffffffffu, c0, 2);
            c0 += __shfl_xor_sync(0xffffffffu, c0, 1);
            if ((lane & 7) == 0) {
                int q = g * 4 + ((lane >> 4) & 1) + ((lane >> 3) & 1) * 2;
                su.p.qsm[q][o] = c0 + bias;
            }
        }
    }

    // hpart = W1b @ qin + b1
    for (int oi = 0; oi < 8; oi++) {
        int o = w * 8 + oi;
        const float* wr = W1 + (size_t)o * FFNIN + LAT;
        float wreg[12];
        #pragma unroll
        for (int r = 0; r < 12; r++) wreg[r] = wr[lane + 32 * r];
        float bias = b1[o];
        #pragma unroll
        for (int g = 0; g < 2; g++) {
            float p[4];
            #pragma unroll
            for (int qq = 0; qq < 4; qq++) {
                float s = 0.f;
                #pragma unroll
                for (int r = 0; r < 12; r++)
                    s = fmaf(wreg[r], su.p.qin[g * 4 + qq][lane + 32 * r], s);
                p[qq] = s;
            }
            float a0 = mrg(p[0], p[1], 16, lane), a1 = mrg(p[2], p[3], 16, lane);
            float c0 = mrg(a0, a1, 8, lane);
            c0 += __shfl_xor_sync(0xffffffffu, c0, 4);
            c0 += __shfl_xor_sync(0xffffffffu, c0, 2);
            c0 += __shfl_xor_sync(0xffffffffu, c0, 1);
            if ((lane & 7) == 0) {
                int q = g * 4 + ((lane >> 4) & 1) + ((lane >> 3) & 1) * 2;
                g_hpart[(size_t)(b0 + q) * LAT + o] = c0 + bias;
            }
        }
    }
    __syncthreads();

    // qk = Wk^T q  (smem-staged Wk tiles)
    {
        float acc[GQ];
        #pragma unroll
        for (int q = 0; q < GQ; q++) acc[q] = 0.f;
        for (int j0 = 0; j0 < LAT; j0 += 16) {
            __syncthreads();
            for (int m2 = t; m2 < 16 * 96; m2 += 512) {
                int jj = m2 / 96, c4 = m2 % 96;
                *(float4*)&su.p.wk_sm[jj][c4 * 4] =
                    ((const float4*)(Wk + (size_t)(j0 + jj) * INDIM))[c4];
            }
            __syncthreads();
            if (t < INDIM) {
                #pragma unroll
                for (int jj = 0; jj < 16; jj++) {
                    float wv = su.p.wk_sm[jj][t];
                    #pragma unroll
                    for (int q = 0; q < GQ; q++)
                        acc[q] = fmaf(su.p.qsm[q][j0 + jj], wv, acc[q]);
                }
            }
        }
        if (t < INDIM) {
            #pragma unroll
            for (int q = 0; q < GQ; q++) g_qk[(size_t)(b0 + q) * INDIM + t] = acc[q];
        }
    }
    if (t == 0) g_cvec[blockIdx.x] = su.p.cvec;
}

// ---------------------------------------------------------------------------
// Kernel 2: gather + online softmax + folded FFN epilogue (R8/R11 verbatim).
// 1024 blocks x 512 thr. Writes final output directly.
// ---------------------------------------------------------------------------
__global__ void __launch_bounds__(512, 2) k_gather(
    const float* __restrict__ x, const float* __restrict__ mem,
    const float* __restrict__ dt, const float* __restrict__ W2,
    const float* __restrict__ b2, float* __restrict__ out)
{
    int b = blockIdx.x, t = threadIdx.x, lane = t & 31, w = t >> 5;
    __shared__ float s_qk[INDIM];
    __shared__ float s_part[16][INDIM];
    __shared__ float s_m[16], s_l[16];
    __shared__ float s_acc[INDIM];
    __shared__ float s_hp[LAT];
    __shared__ float s_h[LAT];

    if (t < INDIM) s_qk[t] = g_qk[(size_t)b * INDIM + t];
    if (t >= INDIM && t < INDIM + LAT) {
        int o = t - INDIM;
        s_hp[o] = g_hpart[(size_t)b * LAT + o] + g_cvec[o];
    }
    __syncthreads();
    int cnt = g_cnt[b];
    const float scale = 0.08838834764831845f;   // 1/sqrt(128)

    float m = -INFINITY, l = 0.f;
    float racc[12];
    #pragma unroll
    for (int r = 0; r < 12; r++) racc[r] = 0.f;

    int p = w;
    float rowv[12];
    if (p < cnt) {
        int n = g_list[b * CAP + p];
        const float* px = x + (size_t)n * LAT;
        const float* pm = mem + (size_t)n * LAT;
        const float* pd = dt + (size_t)n * LAT;
        #pragma unroll
        for (int r = 0; r < 4; r++) rowv[r]     = px[lane + 32 * r];
        #pragma unroll
        for (int r = 0; r < 4; r++) rowv[4 + r] = pm[lane + 32 * r];
        #pragma unroll
        for (int r = 0; r < 4; r++) rowv[8 + r] = pd[lane + 32 * r];
    }
    while (p < cnt) {
        int pn = p + 16;
        float rnext[12];
        if (pn < cnt) {
            int n = g_list[b * CAP + pn];
            const float* px = x + (size_t)n * LAT;
            const float* pm = mem + (size_t)n * LAT;
            const float* pd = dt + (size_t)n * LAT;
            #pragma unroll
            for (int r = 0; r < 4; r++) rnext[r]     = px[lane + 32 * r];
            #pragma unroll
            for (int r = 0; r < 4; r++) rnext[4 + r] = pm[lane + 32 * r];
            #pragma unroll
            for (int r = 0; r < 4; r++) rnext[8 + r] = pd[lane + 32 * r];
        }
        float dot = 0.f;
        #pragma unroll
        for (int r = 0; r < 12; r++) dot = fmaf(rowv[r], s_qk[32 * r + lane], dot);
        #pragma unroll
        for (int off = 16; off; off >>= 1) dot += __shfl_xor_sync(0xffffffffu, dot, off);
        float s = dot * scale;                  // qbias dropped: softmax shift-invariant
        float mnew = fmaxf(m, s);
        float corr = __expf(m - mnew);
        float e = __expf(s - mnew);
        l = l * corr + e;
        m = mnew;
        #pragma unroll
        for (int r = 0; r < 12; r++) racc[r] = fmaf(racc[r], corr, e * rowv[r]);
        #pragma unroll
        for (int r = 0; r < 12; r++) rowv[r] = rnext[r];
        p = pn;
    }
    #pragma unroll
    for (int r = 0; r < 12; r++) s_part[w][32 * r + lane] = racc[r];
    if (lane == 0) { s_m[w] = m; s_l[w] = l; }
    __syncthreads();

    // merge 16 warp-local online-softmax states -> s_acc
    {
        float M = s_m[0];
        #pragma unroll
        for (int i = 1; i < 16; i++) M = fmaxf(M, s_m[i]);
        float L = 0.f;
        float ef[16];
        #pragma unroll
        for (int i = 0; i < 16; i++) { ef[i] = __expf(s_m[i] - M); L += s_l[i] * ef[i]; }
        float invL = 1.f / L;
        if (t < INDIM) {
            float sum = 0.f;
            #pragma unroll
            for (int i = 0; i < 16; i++) sum = fmaf(s_part[i][t], ef[i], sum);
            s_acc[t] = sum * invL;
        }
    }
    __syncthreads();

    // FFN stage 1: h = relu(Wfold @ acc + hpart)
    for (int oi = 0; oi < 8; oi++) {
        int o = w * 8 + oi;
        const float* wr = g_Wfold + (size_t)o * INDIM;
        float dot = 0.f;
        #pragma unroll
        for (int r = 0; r < 12; r++) dot = fmaf(wr[lane + 32 * r], s_acc[lane + 32 * r], dot);
        #pragma unroll
        for (int off = 16; off; off >>= 1) dot += __shfl_xor_sync(0xffffffffu, dot, off);
        if (lane == 0) s_h[o] = fmaxf(dot + s_hp[o], 0.f);
    }
    __syncthreads();

    // FFN stage 2: out = W2 @ h + b2
    for (int oi = 0; oi < 8; oi++) {
        int o = w * 8 + oi;
        const float* wr = W2 + (size_t)o * LAT;
        float dot = 0.f;
        #pragma unroll
        for (int r = 0; r < 4; r++) dot = fmaf(wr[lane + 32 * r], s_h[lane + 32 * r], dot);
        #pragma unroll
        for (int off = 16; off; off >>= 1) dot += __shfl_xor_sync(0xffffffffu, dot, off);
        if (lane == 0) out[(size_t)b * LAT + o] = dot + b2[o];
    }
}

// ---------------------------------------------------------------------------
extern "C" void kernel_launch(void* const* d_in, const int* in_sizes, int n_in,
                              void* d_out, int out_size)
{
    const float* x    = (const float*)d_in[0];
    const float* mem  = (const float*)d_in[1];
    const float* dt   = (const float*)d_in[2];
    const float* tart = (const float*)d_in[3];
    const unsigned char* mask = (const unsigned char*)d_in[4];
    const int*   tidx = (const int*)d_in[5];
    const float* Wq = (const float*)d_in[6];
    const float* bq = (const float*)d_in[7];
    const float* Wk = (const float*)d_in[8];
    // bk (d_in[9]) unused: q.bk cancels in softmax
    const float* Wv = (const float*)d_in[10];
    const float* bv = (const float*)d_in[11];
    const float* W1 = (const float*)d_in[12];
    const float* b1 = (const float*)d_in[13];
    const float* W2 = (const float*)d_in[14];
    const float* b2 = (const float*)d_in[15];
    float* out = (float*)d_out;

    // Single stream, structural overlap inside k_main (prep blocks + scan blocks).
    k_main<<<PREPB + BB, 512>>>(x, mem, tart, tidx, Wq, bq, Wk, W1, b1, Wv, bv, mask);
    k_gather<<<BB, 512>>>(x, mem, dt, W2, b2, out);
}

// round 13
// speedup vs baseline: 1.3672x; 1.0186x over previous
#include <cuda_runtime.h>
#include <math.h>

// Problem constants (fixed shapes per reference)
#define NN 100000
#define BB 1024
#define LAT 128
#define INDIM 384      // NODE_DIM + 2*LATENT
#define FFNIN 512      // LATENT + IN_DIM
#define CAP 512        // neighbor list capacity (mean ~50)
#define GQ 8           // queries per prep/epi block
#define PREPB 128      // number of prep blocks (BB/GQ)

// Scratch (device globals; no allocation allowed)
__device__ float g_qk[BB * INDIM];
__device__ float g_hpart[BB * LAT];     // W1b @ q_input + b1
__device__ float g_acc[BB * INDIM];     // softmax-weighted kv sum
__device__ float g_Wfold[LAT * INDIM];  // W1a @ Wv
__device__ float g_cvec[LAT];           // W1a @ bv
__device__ int   g_list[BB * CAP];
__device__ int   g_cnt[BB];

// Merge two partial-sum arrays across xor-lane distance `bit`
__device__ __forceinline__ float mrg(float a, float b, int bit, int lane) {
    float keep = (lane & bit) ? b : a;
    float send = (lane & bit) ? a : b;
    return keep + __shfl_xor_sync(0xffffffffu, send, bit);
}

// Shared-memory union: prep path needs ~41.5KB, scan path ~2KB.
struct SmemPrep {
    float qin[GQ][INDIM];
    float qsm[GQ][LAT];
    float wk_sm[16][INDIM];
    float w1a[LAT];
    float cvec;
    int   sidx[GQ];
};
struct SmemScan {
    int idx[CAP];
    int cnt;
};
union SmemU {
    SmemPrep p;
    SmemScan s;
};

#define PROC4(u, base) \
    if (u.x | u.y | u.z | u.w) { \
        if (u.x) { int sl = atomicAdd(cntp, 1); if (sl < CAP) idxp[sl] = (base) * 4 + 0; } \
        if (u.y) { int sl = atomicAdd(cntp, 1); if (sl < CAP) idxp[sl] = (base) * 4 + 1; } \
        if (u.z) { int sl = atomicAdd(cntp, 1); if (sl < CAP) idxp[sl] = (base) * 4 + 2; } \
        if (u.w) { int sl = atomicAdd(cntp, 1); if (sl < CAP) idxp[sl] = (base) * 4 + 3; } }

// ---------------------------------------------------------------------------
// FAT kernel (R12-proven): blocks [0,128) = prep ; [128, 1152) = scan.
// ---------------------------------------------------------------------------
__global__ void __launch_bounds__(512, 2) k_main(
    const float* __restrict__ x, const float* __restrict__ mem,
    const float* __restrict__ tart, const int* __restrict__ tidx,
    const float* __restrict__ Wq, const float* __restrict__ bq,
    const float* __restrict__ Wk, const float* __restrict__ W1,
    const float* __restrict__ b1, const float* __restrict__ Wv,
    const float* __restrict__ bv, const unsigned char* __restrict__ maskb)
{
    __shared__ SmemU su;
    int t = threadIdx.x, lane = t & 31, w = t >> 5;

    if (blockIdx.x >= PREPB) {
        // ================= SCAN PATH (512 threads) =================
        int b = blockIdx.x - PREPB;
        int* idxp = su.s.idx;
        int* cntp = &su.s.cnt;
        if (t == 0) *cntp = 0;
        __syncthreads();

        const uint4* row = (const uint4*)(maskb + (size_t)b * NN * 4);
        const int NW = NN / 4;                    // 25000 uint4
        int i = t;
        for (; i + 1536 < NW; i += 2048) {
            uint4 a  = row[i];
            uint4 b4 = row[i + 512];
            uint4 c4 = row[i + 1024];
            uint4 d4 = row[i + 1536];
            PROC4(a, i) PROC4(b4, i + 512) PROC4(c4, i + 1024) PROC4(d4, i + 1536)
        }
        for (; i < NW; i += 512) { uint4 u = row[i]; PROC4(u, i) }

        __syncthreads();
        int cnt = min(*cntp, CAP);
        if (cnt == 0) {
            if (t == 0) { g_list[b * CAP] = tidx[b]; g_cnt[b] = 1; }
            return;
        }
        for (int m2 = t; m2 < cnt; m2 += 512) g_list[b * CAP + m2] = idxp[m2];
        if (t == 0) g_cnt[b] = cnt;
        return;
    }

    // ================= PREP PATH =================
    int b0 = blockIdx.x * GQ;
    if (t < GQ) su.p.sidx[t] = tidx[b0 + t];
    if (t < LAT) su.p.w1a[t] = W1[(size_t)blockIdx.x * FFNIN + t];
    __syncthreads();

    // Wfold row: Wfold[o][c] = sum_j w1a[j] * Wv[j][c]  (o = blockIdx)
    if (t < INDIM) {
        float s = 0.f;
        #pragma unroll 8
        for (int j = 0; j < LAT; j++) s = fmaf(su.p.w1a[j], Wv[(size_t)j * INDIM + t], s);
        g_Wfold[(size_t)blockIdx.x * INDIM + t] = s;
    }
    // cvec[o] = w1a . bv
    if (w == 15) {
        float v = 0.f;
        #pragma unroll
        for (int r = 0; r < 4; r++) v = fmaf(su.p.w1a[lane + 32 * r], bv[lane + 32 * r], v);
        #pragma unroll
        for (int off = 16; off; off >>= 1) v += __shfl_xor_sync(0xffffffffu, v, off);
        if (lane == 0) su.p.cvec = v;
    }

    // gather q_input
    for (int m2 = t; m2 < GQ * 96; m2 += 512) {
        int q = m2 / 96, c4 = m2 % 96;
        float4 v;
        if (c4 < 32)      v = ((const float4*)(x    + (size_t)su.p.sidx[q] * LAT))[c4];
        else if (c4 < 64) v = ((const float4*)(mem  + (size_t)su.p.sidx[q] * LAT))[c4 - 32];
        else              v = ((const float4*)(tart + (size_t)(b0 + q) * LAT))[c4 - 64];
        *(float4*)&su.p.qin[q][c4 * 4] = v;
    }
    __syncthreads();

    // q = Wq @ qin + bq  (16 warps x 8 outputs; 2 groups of 4 queries)
    for (int oi = 0; oi < 8; oi++) {
        int o = w * 8 + oi;
        const float* wr = Wq + (size_t)o * INDIM;
        float wreg[12];
        #pragma unroll
        for (int r = 0; r < 12; r++) wreg[r] = wr[lane + 32 * r];
        float bias = bq[o];
        #pragma unroll
        for (int g = 0; g < 2; g++) {
            float p[4];
            #pragma unroll
            for (int qq = 0; qq < 4; qq++) {
                float s = 0.f;
                #pragma unroll
                for (int r = 0; r < 12; r++)
                    s = fmaf(wreg[r], su.p.qin[g * 4 + qq][lane + 32 * r], s);
                p[qq] = s;
            }
            float a0 = mrg(p[0], p[1], 16, lane), a1 = mrg(p[2], p[3], 16, lane);
            float c0 = mrg(a0, a1, 8, lane);
            c0 += __shfl_xor_sync(0xffffffffu, c0, 4);
            c0 += __shfl_xor_sync(0xffffffffu, c0, 2);
            c0 += __shfl_xor_sync(0xffffffffu, c0, 1);
            if ((lane & 7) == 0) {
                int q = g * 4 + ((lane >> 4) & 1) + ((lane >> 3) & 1) * 2;
                su.p.qsm[q][o] = c0 + bias;
            }
        }
    }

    // hpart = W1b @ qin + b1
    for (int oi = 0; oi < 8; oi++) {
        int o = w * 8 + oi;
        const float* wr = W1 + (size_t)o * FFNIN + LAT;
        float wreg[12];
        #pragma unroll
        for (int r = 0; r < 12; r++) wreg[r] = wr[lane + 32 * r];
        float bias = b1[o];
        #pragma unroll
        for (int g = 0; g < 2; g++) {
            float p[4];
            #pragma unroll
            for (int qq = 0; qq < 4; qq++) {
                float s = 0.f;
                #pragma unroll
                for (int r = 0; r < 12; r++)
                    s = fmaf(wreg[r], su.p.qin[g * 4 + qq][lane + 32 * r], s);
                p[qq] = s;
            }
            float a0 = mrg(p[0], p[1], 16, lane), a1 = mrg(p[2], p[3], 16, lane);
            float c0 = mrg(a0, a1, 8, lane);
            c0 += __shfl_xor_sync(0xffffffffu, c0, 4);
            c0 += __shfl_xor_sync(0xffffffffu, c0, 2);
            c0 += __shfl_xor_sync(0xffffffffu, c0, 1);
            if ((lane & 7) == 0) {
                int q = g * 4 + ((lane >> 4) & 1) + ((lane >> 3) & 1) * 2;
                g_hpart[(size_t)(b0 + q) * LAT + o] = c0 + bias;
            }
        }
    }
    __syncthreads();

    // qk = Wk^T q  (smem-staged Wk tiles)
    {
        float acc[GQ];
        #pragma unroll
        for (int q = 0; q < GQ; q++) acc[q] = 0.f;
        for (int j0 = 0; j0 < LAT; j0 += 16) {
            __syncthreads();
            for (int m2 = t; m2 < 16 * 96; m2 += 512) {
                int jj = m2 / 96, c4 = m2 % 96;
                *(float4*)&su.p.wk_sm[jj][c4 * 4] =
                    ((const float4*)(Wk + (size_t)(j0 + jj) * INDIM))[c4];
            }
            __syncthreads();
            if (t < INDIM) {
                #pragma unroll
                for (int jj = 0; jj < 16; jj++) {
                    float wv = su.p.wk_sm[jj][t];
                    #pragma unroll
                    for (int q = 0; q < GQ; q++)
                        acc[q] = fmaf(su.p.qsm[q][j0 + jj], wv, acc[q]);
                }
            }
        }
        if (t < INDIM) {
            #pragma unroll
            for (int q = 0; q < GQ; q++) g_qk[(size_t)(b0 + q) * INDIM + t] = acc[q];
        }
    }
    if (t == 0) g_cvec[blockIdx.x] = su.p.cvec;
}

// ---------------------------------------------------------------------------
// Kernel 2: PURE gather + online softmax -> g_acc (R10-proven, 26.6us).
// ---------------------------------------------------------------------------
__global__ void __launch_bounds__(512) k_gather(
    const float* __restrict__ x, const float* __restrict__ mem,
    const float* __restrict__ dt)
{
    int b = blockIdx.x, t = threadIdx.x, lane = t & 31, w = t >> 5;
    __shared__ float s_qk[INDIM];
    __shared__ float s_part[16][INDIM];
    __shared__ float s_m[16], s_l[16];

    if (t < INDIM) s_qk[t] = g_qk[(size_t)b * INDIM + t];
    __syncthreads();
    int cnt = g_cnt[b];
    const float scale = 0.08838834764831845f;   // 1/sqrt(128)

    float m = -INFINITY, l = 0.f;
    float racc[12];
    #pragma unroll
    for (int r = 0; r < 12; r++) racc[r] = 0.f;

    int p = w;
    float rowv[12];
    if (p < cnt) {
        int n = g_list[b * CAP + p];
        const float* px = x + (size_t)n * LAT;
        const float* pm = mem + (size_t)n * LAT;
        const float* pd = dt + (size_t)n * LAT;
        #pragma unroll
        for (int r = 0; r < 4; r++) rowv[r]     = px[lane + 32 * r];
        #pragma unroll
        for (int r = 0; r < 4; r++) rowv[4 + r] = pm[lane + 32 * r];
        #pragma unroll
        for (int r = 0; r < 4; r++) rowv[8 + r] = pd[lane + 32 * r];
    }
    while (p < cnt) {
        int pn = p + 16;
        float rnext[12];
        if (pn < cnt) {
            int n = g_list[b * CAP + pn];
            const float* px = x + (size_t)n * LAT;
            const float* pm = mem + (size_t)n * LAT;
            const float* pd = dt + (size_t)n * LAT;
            #pragma unroll
            for (int r = 0; r < 4; r++) rnext[r]     = px[lane + 32 * r];
            #pragma unroll
            for (int r = 0; r < 4; r++) rnext[4 + r] = pm[lane + 32 * r];
            #pragma unroll
            for (int r = 0; r < 4; r++) rnext[8 + r] = pd[lane + 32 * r];
        }
        float dot = 0.f;
        #pragma unroll
        for (int r = 0; r < 12; r++) dot = fmaf(rowv[r], s_qk[32 * r + lane], dot);
        #pragma unroll
        for (int off = 16; off; off >>= 1) dot += __shfl_xor_sync(0xffffffffu, dot, off);
        float s = dot * scale;                  // q.bk dropped (softmax-invariant)
        float mnew = fmaxf(m, s);
        float corr = __expf(m - mnew);
        float e = __expf(s - mnew);
        l = l * corr + e;
        m = mnew;
        #pragma unroll
        for (int r = 0; r < 12; r++) racc[r] = fmaf(racc[r], corr, e * rowv[r]);
        #pragma unroll
        for (int r = 0; r < 12; r++) rowv[r] = rnext[r];
        p = pn;
    }
    #pragma unroll
    for (int r = 0; r < 12; r++) s_part[w][32 * r + lane] = racc[r];
    if (lane == 0) { s_m[w] = m; s_l[w] = l; }
    __syncthreads();

    float M = s_m[0];
    #pragma unroll
    for (int i = 1; i < 16; i++) M = fmaxf(M, s_m[i]);
    float L = 0.f;
    float ef[16];
    #pragma unroll
    for (int i = 0; i < 16; i++) { ef[i] = __expf(s_m[i] - M); L += s_l[i] * ef[i]; }
    float invL = 1.f / L;
    if (t < INDIM) {
        float sum = 0.f;
        #pragma unroll
        for (int i = 0; i < 16; i++) sum = fmaf(s_part[i][t], ef[i], sum);
        g_acc[(size_t)b * INDIM + t] = sum * invL;
    }
}

// ---------------------------------------------------------------------------
// Kernel 3: folded epilogue, 128 blocks x 512, GQ=8, 2 groups of 4 queries
// (register-safe).  h = relu(Wfold@acc + hpart + cvec) ; out = W2@h + b2
// ---------------------------------------------------------------------------
__global__ void __launch_bounds__(512, 2) k_epi(
    const float* __restrict__ W2, const float* __restrict__ b2,
    float* __restrict__ out)
{
    int b0 = blockIdx.x * GQ;
    int t = threadIdx.x, lane = t & 31, w = t >> 5;
    __shared__ float acc[GQ][INDIM];
    __shared__ float hp[GQ][LAT];
    __shared__ float h[GQ][LAT];

    for (int m = t; m < GQ * 96; m += 512) {
        int q = m / 96, c4 = m % 96;
        *(float4*)&acc[q][c4 * 4] = *(const float4*)&g_acc[(size_t)(b0 + q) * INDIM + c4 * 4];
    }
    for (int m = t; m < GQ * LAT; m += 512) {
        int q = m >> 7, o = m & 127;
        hp[q][o] = g_hpart[(size_t)(b0 + q) * LAT + o] + g_cvec[o];
    }
    __syncthreads();

    // stage 1: h = relu(Wfold @ acc + hp)  (2 groups of 4 queries)
    for (int oi = 0; oi < 8; oi++) {
        int o = w * 8 + oi;
        const float* wr = g_Wfold + (size_t)o * INDIM;
        float wreg[12];
        #pragma unroll
        for (int r = 0; r < 12; r++) wreg[r] = wr[lane + 32 * r];
        #pragma unroll
        for (int g = 0; g < 2; g++) {
            float p[4];
            #pragma unroll
            for (int qq = 0; qq < 4; qq++) {
                float s = 0.f;
                #pragma unroll
                for (int r = 0; r < 12; r++)
                    s = fmaf(wreg[r], acc[g * 4 + qq][lane + 32 * r], s);
                p[qq] = s;
            }
            float a0 = mrg(p[0], p[1], 16, lane), a1 = mrg(p[2], p[3], 16, lane);
            float c0 = mrg(a0, a1, 8, lane);
            c0 += __shfl_xor_sync(0xffffffffu, c0, 4);
            c0 += __shfl_xor_sync(0xffffffffu, c0, 2);
            c0 += __shfl_xor_sync(0xffffffffu, c0, 1);
            if ((lane & 7) == 0) {
                int q = g * 4 + ((lane >> 4) & 1) + ((lane >> 3) & 1) * 2;
                h[q][o] = fmaxf(c0 + hp[q][o], 0.f);
            }
        }
    }
    __syncthreads();

    // stage 2: out = W2 @ h + b2  (2 groups of 4 queries)
    for (int oi = 0; oi < 8; oi++) {
        int o = w * 8 + oi;
        const float* wr = W2 + (size_t)o * LAT;
        float wreg[4];
        #pragma unroll
        for (int r = 0; r < 4; r++) wreg[r] = wr[lane + 32 * r];
        float bias = b2[o];
        #pragma unroll
        for (int g = 0; g < 2; g++) {
            float p[4];
            #pragma unroll
            for (int qq = 0; qq < 4; qq++) {
                float s = 0.f;
                #pragma unroll
                for (int r = 0; r < 4; r++)
                    s = fmaf(wreg[r], h[g * 4 + qq][lane + 32 * r], s);
                p[qq] = s;
            }
            float a0 = mrg(p[0], p[1], 16, lane), a1 = mrg(p[2], p[3], 16, lane);
            float c0 = mrg(a0, a1, 8, lane);
            c0 += __shfl_xor_sync(0xffffffffu, c0, 4);
            c0 += __shfl_xor_sync(0xffffffffu, c0, 2);
            c0 += __shfl_xor_sync(0xffffffffu, c0, 1);
            if ((lane & 7) == 0) {
                int q = g * 4 + ((lane >> 4) & 1) + ((lane >> 3) & 1) * 2;
                out[(size_t)(b0 + q) * LAT + o] = c0 + bias;
            }
        }
    }
}

// ---------------------------------------------------------------------------
extern "C" void kernel_launch(void* const* d_in, const int* in_sizes, int n_in,
                              void* d_out, int out_size)
{
    const float* x    = (const float*)d_in[0];
    const float* mem  = (const float*)d_in[1];
    const float* dt   = (const float*)d_in[2];
    const float* tart = (const float*)d_in[3];
    const unsigned char* mask = (const unsigned char*)d_in[4];
    const int*   tidx = (const int*)d_in[5];
    const float* Wq = (const float*)d_in[6];
    const float* bq = (const float*)d_in[7];
    const float* Wk = (const float*)d_in[8];
    // bk (d_in[9]) unused: q.bk cancels in softmax
    const float* Wv = (const float*)d_in[10];
    const float* bv = (const float*)d_in[11];
    const float* W1 = (const float*)d_in[12];
    const float* b1 = (const float*)d_in[13];
    const float* W2 = (const float*)d_in[14];
    const float* b2 = (const float*)d_in[15];
    float* out = (float*)d_out;

    k_main<<<PREPB + BB, 512>>>(x, mem, tart, tidx, Wq, bq, Wk, W1, b1, Wv, bv, mask);
    k_gather<<<BB, 512>>>(x, mem, dt);
    k_epi<<<BB / GQ, 512>>>(W2, b2, out);
}